// round 7
// baseline (speedup 1.0000x reference)
#include <cuda_runtime.h>
#include <math.h>

#define MAXN 100000
#define MAXE 1600000
#define MAXET (MAXE + MAXN)
#define DH 64
#define NG 128
#define NC 10
#define NEG 0.2f
#define TN 16   // nodes per transform tile

// ---------------- static device scratch ----------------
__device__ int   g_is64;
__device__ int   g_esrc[MAXE];
__device__ int   g_edst[MAXE];
__device__ int   g_batch[MAXN];
__device__ int   g_deg[MAXN];
__device__ int   g_ptr[MAXN + 1];
__device__ int   g_src[MAXET];     // CSR src per slot
__device__ int   g_dstc[MAXET];    // CSR dst per slot (companion)
__device__ float g_w[MAXET];       // per-edge exp weight
__device__ float g_sum[MAXN];      // per-node softmax denominator
__device__ __align__(16) float g_hA[MAXN * DH];
__device__ __align__(16) float g_hB[MAXN * DH];
__device__ float g_as[MAXN];
__device__ float g_ad[MAXN];
__device__ __align__(16) float g_pool[NG * DH];
__device__ int   g_cnt[NG];
__device__ int   g_part[64];

// ---------------- dtype detection: int64 (odd 32-bit words all zero) vs int32 ----------------
__global__ void k_detect(const unsigned int* __restrict__ w, int E) {
    __shared__ int nz;
    if (threadIdx.x == 0) nz = 0;
    __syncthreads();
    for (int k = threadIdx.x; k < 1024; k += blockDim.x) {
        long long pos = 2ll * ((long long)k * (E - 1) / 1024) + 1;
        if (w[pos] != 0u) atomicAdd(&nz, 1);
    }
    __syncthreads();
    if (threadIdx.x == 0) g_is64 = (nz == 0) ? 1 : 0;
}

// ---------------- init ----------------
__global__ void k_init(int n) {
    int i = blockIdx.x * blockDim.x + threadIdx.x;
    if (i < n) {
        g_deg[i] = 1;       // self loop pre-counted
        g_sum[i] = 0.f;     // layer-1 denominator
    }
    if (i < NG * DH) g_pool[i] = 0.f;
    if (i < NG) g_cnt[i] = 0;
}

// ---------------- convert edges to int32 (clamped) + fused degree count ----------------
__global__ void k_convert_edges(const void* __restrict__ ei, int E, int n) {
    int i = blockIdx.x * blockDim.x + threadIdx.x;
    if (i >= E) return;
    int s, d;
    if (g_is64) {
        const long long* p = (const long long*)ei;
        s = (int)p[i];
        d = (int)p[(size_t)E + i];
    } else {
        const int* p = (const int*)ei;
        s = p[i];
        d = p[E + i];
    }
    s = min(max(s, 0), n - 1);
    d = min(max(d, 0), n - 1);
    g_esrc[i] = s;
    g_edst[i] = d;
    atomicAdd(&g_deg[d], 1);
}

__global__ void k_convert_batch(const void* __restrict__ b, int n) {
    int i = blockIdx.x * blockDim.x + threadIdx.x;
    if (i >= n) return;
    int v;
    if (g_is64) v = (int)((const long long*)b)[i];
    else        v = ((const int*)b)[i];
    g_batch[i] = min(max(v, 0), NG - 1);
}

// ---------------- 3-kernel exclusive scan: g_deg -> g_ptr ----------------
__global__ void k_scan1(int n) {
    __shared__ int sh[256];
    int base = blockIdx.x * 2048 + threadIdx.x * 8;
    int s = 0;
#pragma unroll
    for (int k = 0; k < 8; k++) {
        int idx = base + k;
        if (idx < n) s += g_deg[idx];
    }
    sh[threadIdx.x] = s;
    __syncthreads();
    for (int o = 128; o > 0; o >>= 1) {
        if (threadIdx.x < o) sh[threadIdx.x] += sh[threadIdx.x + o];
        __syncthreads();
    }
    if (threadIdx.x == 0) g_part[blockIdx.x] = sh[0];
}

__global__ void k_scan2(int nb, int n) {
    if (threadIdx.x == 0 && blockIdx.x == 0) {
        int run = 0;
        for (int b = 0; b < nb; b++) {
            int t = g_part[b];
            g_part[b] = run;
            run += t;
        }
        g_ptr[n] = run;
    }
}

__global__ void k_scan3(int n) {
    __shared__ int sh[256];
    int base = blockIdx.x * 2048 + threadIdx.x * 8;
    int loc[8];
    int s = 0;
#pragma unroll
    for (int k = 0; k < 8; k++) {
        int idx = base + k;
        loc[k] = s;
        if (idx < n) s += g_deg[idx];
    }
    sh[threadIdx.x] = s;
    __syncthreads();
    for (int o = 1; o < 256; o <<= 1) {
        int t = 0;
        if ((int)threadIdx.x >= o) t = sh[threadIdx.x - o];
        __syncthreads();
        sh[threadIdx.x] += t;
        __syncthreads();
    }
    int off = g_part[blockIdx.x] + sh[threadIdx.x] - s;
#pragma unroll
    for (int k = 0; k < 8; k++) {
        int idx = base + k;
        if (idx < n) {
            g_ptr[idx] = off + loc[k];
            g_deg[idx] = 0;
        }
    }
}

// ---------------- scatter edges (+self loops) into CSR (src + dst companion) ----------------
__global__ void k_scatter(int E, int n) {
    int i = blockIdx.x * blockDim.x + threadIdx.x;
    int tot = E + n;
    if (i >= tot) return;
    int s, d;
    if (i < E) { s = g_esrc[i]; d = g_edst[i]; }
    else       { s = d = i - E; }
    int p = atomicAdd(&g_deg[d], 1);
    int slot = g_ptr[d] + p;
    g_src[slot] = s;
    g_dstc[slot] = d;
}

// ---------------- node transform, layer 1 (in-dim 3) ----------------
__global__ void k_transform_in(const float* __restrict__ x, const float* __restrict__ pos,
                               const float* __restrict__ W, const float* __restrict__ asrc,
                               const float* __restrict__ adst, int n) {
    __shared__ float ss[8], sd[8];
    int g = threadIdx.x >> 6;
    int c = threadIdx.x & 63;
    int node = blockIdx.x * 4 + g;
    bool valid = node < n;
    float h = 0.f;
    if (valid) {
        float p0 = pos[node * 2];
        float p1 = pos[node * 2 + 1];
        float xv = x[node];
        h = p0 * W[c] + p1 * W[64 + c] + xv * W[128 + c];
        g_hB[(size_t)node * DH + c] = h;
    }
    float vs = valid ? h * asrc[c] : 0.f;
    float vd = valid ? h * adst[c] : 0.f;
#pragma unroll
    for (int o = 16; o > 0; o >>= 1) {
        vs += __shfl_xor_sync(0xffffffffu, vs, o);
        vd += __shfl_xor_sync(0xffffffffu, vd, o);
    }
    int w = threadIdx.x >> 5;
    if ((threadIdx.x & 31) == 0) { ss[w] = vs; sd[w] = vd; }
    __syncthreads();
    if (valid && (threadIdx.x & 63) == 0) {
        g_as[node] = ss[w] + ss[w + 1];
        g_ad[node] = sd[w] + sd[w + 1];
    }
}

// ---------------- node transform, layers 2/3: g_hA -> g_hB (zeroes g_sum) ----------------
__global__ __launch_bounds__(256) void k_transform64(const float* __restrict__ W,
                                                     const float* __restrict__ asrc,
                                                     const float* __restrict__ adst,
                                                     int n, int ntiles) {
    __shared__ float4 sW[DH * 16];
    __shared__ float s_h[TN][DH + 1];
    int tid = threadIdx.x;
    for (int i = tid; i < DH * 16; i += 256) sW[i] = ((const float4*)W)[i];
    int g = tid >> 4;
    int c4 = tid & 15;
    float4 as4 = ((const float4*)asrc)[c4];
    float4 ad4 = ((const float4*)adst)[c4];
    __syncthreads();

    for (int tile = blockIdx.x; tile < ntiles; tile += gridDim.x) {
        int node = tile * TN + g;
        float4 v = (node < n) ? ((const float4*)g_hA)[(size_t)node * 16 + c4]
                              : make_float4(0.f, 0.f, 0.f, 0.f);
        s_h[g][c4 * 4 + 0] = v.x;
        s_h[g][c4 * 4 + 1] = v.y;
        s_h[g][c4 * 4 + 2] = v.z;
        s_h[g][c4 * 4 + 3] = v.w;
        __syncthreads();
        float4 acc = make_float4(0.f, 0.f, 0.f, 0.f);
#pragma unroll
        for (int k = 0; k < DH; k++) {
            float hk = s_h[g][k];
            float4 w4 = sW[k * 16 + c4];
            acc.x += hk * w4.x;
            acc.y += hk * w4.y;
            acc.z += hk * w4.z;
            acc.w += hk * w4.w;
        }
        if (node < n) ((float4*)g_hB)[(size_t)node * 16 + c4] = acc;
        float vs = acc.x * as4.x + acc.y * as4.y + acc.z * as4.z + acc.w * as4.w;
        float vd = acc.x * ad4.x + acc.y * ad4.y + acc.z * ad4.z + acc.w * ad4.w;
#pragma unroll
        for (int o = 8; o > 0; o >>= 1) {
            vs += __shfl_xor_sync(0xffffffffu, vs, o);
            vd += __shfl_xor_sync(0xffffffffu, vd, o);
        }
        if (node < n && c4 == 0) {
            g_as[node] = vs;
            g_ad[node] = vd;
            g_sum[node] = 0.f;   // denominator for this layer's attn pass
        }
        __syncthreads();
    }
}

// ---------------- edge-parallel attention weights: w = exp(lrelu(as[s]+ad[d])) ----------------
__device__ __forceinline__ float lrelu(float t) { return t > 0.f ? t : NEG * t; }

__global__ __launch_bounds__(256) void k_attn(int ET) {
    int j = blockIdx.x * blockDim.x + threadIdx.x;
    if (j >= ET) return;
    int s = g_src[j];
    int d = g_dstc[j];
    float e = lrelu(g_as[s] + g_ad[d]);
    float w = __expf(e);            // no max-sub: |e| << 88, cannot overflow
    g_w[j] = w;
    atomicAdd(&g_sum[d], w);
}

// ---------------- GAT aggregation: warp/node, paired-edge float4 loads ----------------
__global__ __launch_bounds__(256) void k_aggregate(const float* __restrict__ bias, int n) {
    int node = blockIdx.x * 8 + (threadIdx.x >> 5);
    if (node >= n) return;
    int lane = threadIdx.x & 31;
    int half = lane >> 4;
    int qc = lane & 15;
    int start = g_ptr[node];
    int end = g_ptr[node + 1];
    int deg = end - start;   // >= 1
    float invs = 1.f / (g_sum[node] + 1e-16f);
    const float4* __restrict__ h4 = (const float4*)g_hB;
    float4 acc = make_float4(0.f, 0.f, 0.f, 0.f);

    if (deg <= 32) {
        int sv = 0;
        float w = 0.f;
        if (lane < deg) {
            sv = g_src[start + lane];
            w = g_w[start + lane] * invs;
        }
        for (int t = 0; t < deg; t += 2) {
            int idx = t + half;
            int st = __shfl_sync(0xffffffffu, sv, idx & 31);
            float wt = __shfl_sync(0xffffffffu, w, idx & 31);
            if (idx >= deg) wt = 0.f;
            float4 hv = h4[(size_t)st * 16 + qc];
            acc.x += wt * hv.x;
            acc.y += wt * hv.y;
            acc.z += wt * hv.z;
            acc.w += wt * hv.w;
        }
    } else {
        for (int base = start; base < end; base += 32) {
            int cnt = min(32, end - base);
            int sv = 0;
            float w = 0.f;
            if (lane < cnt) {
                sv = g_src[base + lane];
                w = g_w[base + lane] * invs;
            }
            for (int t = 0; t < cnt; t += 2) {
                int idx = t + half;
                int st = __shfl_sync(0xffffffffu, sv, idx & 31);
                float wt = __shfl_sync(0xffffffffu, w, idx & 31);
                if (idx >= cnt) wt = 0.f;
                float4 hv = h4[(size_t)st * 16 + qc];
                acc.x += wt * hv.x;
                acc.y += wt * hv.y;
                acc.z += wt * hv.z;
                acc.w += wt * hv.w;
            }
        }
    }
    acc.x += __shfl_xor_sync(0xffffffffu, acc.x, 16);
    acc.y += __shfl_xor_sync(0xffffffffu, acc.y, 16);
    acc.z += __shfl_xor_sync(0xffffffffu, acc.z, 16);
    acc.w += __shfl_xor_sync(0xffffffffu, acc.w, 16);
    if (half == 0) {
        float4 bb = ((const float4*)bias)[qc];
        ((float4*)g_hA)[(size_t)node * 16 + qc] =
            make_float4(acc.x + bb.x, acc.y + bb.y, acc.z + bb.z, acc.w + bb.w);
    }
}

// ---------------- pooling (sorted batch, run-length pre-aggregation) ----------------
__global__ void k_pool(int n) {
    int c = threadIdx.x & 63;
    int chunk = blockIdx.x * 4 + (threadIdx.x >> 6);
    int i0 = chunk * 64;
    if (i0 >= n) return;
    int iend = min(i0 + 64, n);
    float acc = 0.f;
    int cacc = 0;
    int cur = g_batch[i0];
    for (int i = i0; i < iend; i++) {
        int b = g_batch[i];
        if (b != cur) {
            atomicAdd(&g_pool[cur * DH + c], acc);
            if (c == 0) atomicAdd(&g_cnt[cur], cacc);
            acc = 0.f; cacc = 0; cur = b;
        }
        acc += g_hA[(size_t)i * DH + c];
        cacc++;
    }
    atomicAdd(&g_pool[cur * DH + c], acc);
    if (c == 0) atomicAdd(&g_cnt[cur], cacc);
}

// ---------------- classifier head ----------------
__global__ void k_final(const float* __restrict__ Wl, const float* __restrict__ bl,
                        float* __restrict__ out) {
    int t = blockIdx.x * blockDim.x + threadIdx.x;
    if (t >= NG * NC) return;
    int g = t / NC;
    int cls = t % NC;
    float invc = 1.f / fmaxf((float)g_cnt[g], 1.f);
    float dot = 0.f;
#pragma unroll
    for (int d = 0; d < DH; d++) dot += g_pool[g * DH + d] * Wl[d * NC + cls];
    out[t] = dot * invc + bl[cls];
}

// ---------------- host launcher ----------------
extern "C" void kernel_launch(void* const* d_in, const int* in_sizes, int n_in,
                              void* d_out, int out_size) {
    const float* x = (const float*)d_in[0];
    const float* pos = (const float*)d_in[1];
    const void* ei = d_in[2];
    const void* batch = d_in[3];
    const float* W1 = (const float*)d_in[4];
    const float* as1 = (const float*)d_in[5];
    const float* ad1 = (const float*)d_in[6];
    const float* b1 = (const float*)d_in[7];
    const float* W2 = (const float*)d_in[8];
    const float* as2 = (const float*)d_in[9];
    const float* ad2 = (const float*)d_in[10];
    const float* b2 = (const float*)d_in[11];
    const float* W3 = (const float*)d_in[12];
    const float* as3 = (const float*)d_in[13];
    const float* ad3 = (const float*)d_in[14];
    const float* b3 = (const float*)d_in[15];
    const float* Wl = (const float*)d_in[16];
    const float* bl = (const float*)d_in[17];
    float* out = (float*)d_out;

    int n = in_sizes[0];
    int E = in_sizes[2] / 2;
    int ET = E + n;
    int nb = (n + 2047) / 2048;
    int ntiles = (n + TN - 1) / TN;

    k_detect<<<1, 256>>>((const unsigned int*)ei, E);
    int initT = n;
    if (initT < NG * DH) initT = NG * DH;
    k_init<<<(initT + 255) / 256, 256>>>(n);
    k_convert_edges<<<(E + 255) / 256, 256>>>(ei, E, n);
    k_convert_batch<<<(n + 255) / 256, 256>>>(batch, n);

    k_scan1<<<nb, 256>>>(n);
    k_scan2<<<1, 32>>>(nb, n);
    k_scan3<<<nb, 256>>>(n);
    k_scatter<<<(ET + 255) / 256, 256>>>(E, n);

    int tb = (n + 3) / 4;
    int ab = (n + 7) / 8;
    int eb = (ET + 255) / 256;
    int tg = 1184;

    // layer 1
    k_transform_in<<<tb, 256>>>(x, pos, W1, as1, ad1, n);
    k_attn<<<eb, 256>>>(ET);
    k_aggregate<<<ab, 256>>>(b1, n);
    // layer 2
    k_transform64<<<tg, 256>>>(W2, as2, ad2, n, ntiles);
    k_attn<<<eb, 256>>>(ET);
    k_aggregate<<<ab, 256>>>(b2, n);
    // layer 3
    k_transform64<<<tg, 256>>>(W3, as3, ad3, n, ntiles);
    k_attn<<<eb, 256>>>(ET);
    k_aggregate<<<ab, 256>>>(b3, n);

    int chunks = (n + 63) / 64;
    k_pool<<<(chunks + 3) / 4, 256>>>(n);
    k_final<<<(NG * NC + 255) / 256, 256>>>(Wl, bl, out);
}

// round 8
// speedup vs baseline: 1.2130x; 1.2130x over previous
#include <cuda_runtime.h>
#include <cuda_fp16.h>
#include <math.h>

#define MAXN 100000
#define MAXE 1600000
#define MAXET (MAXE + MAXN)
#define DH 64
#define NG 128
#define NC 10
#define NEG 0.2f
#define TN 16   // nodes per transform tile

// ---------------- static device scratch ----------------
__device__ int   g_is64;
__device__ int   g_esrc[MAXE];
__device__ int   g_edst[MAXE];
__device__ int   g_batch[MAXN];
__device__ int   g_deg[MAXN];
__device__ int   g_ptr[MAXN + 1];
__device__ int   g_src[MAXET];
__device__ __align__(16) float  g_hA[MAXN * DH];      // fp32 layer output
__device__ __align__(16) __half g_hB16[MAXN * DH];    // fp16 gather operand (128B rows)
__device__ float g_as[MAXN];
__device__ float g_ad[MAXN];
__device__ __align__(16) float g_pool[NG * DH];
__device__ int   g_cnt[NG];
__device__ int   g_part[64];

// ---------------- dtype detection: int64 (odd 32-bit words all zero) vs int32 ----------------
__global__ void k_detect(const unsigned int* __restrict__ w, int E) {
    __shared__ int nz;
    if (threadIdx.x == 0) nz = 0;
    __syncthreads();
    for (int k = threadIdx.x; k < 1024; k += blockDim.x) {
        long long pos = 2ll * ((long long)k * (E - 1) / 1024) + 1;
        if (w[pos] != 0u) atomicAdd(&nz, 1);
    }
    __syncthreads();
    if (threadIdx.x == 0) g_is64 = (nz == 0) ? 1 : 0;
}

// ---------------- init ----------------
__global__ void k_init(int n) {
    int i = blockIdx.x * blockDim.x + threadIdx.x;
    if (i < n) g_deg[i] = 1;    // self loop pre-counted
    if (i < NG * DH) g_pool[i] = 0.f;
    if (i < NG) g_cnt[i] = 0;
}

// ---------------- convert edges to int32 (clamped) + fused degree count ----------------
__global__ void k_convert_edges(const void* __restrict__ ei, int E, int n) {
    int i = blockIdx.x * blockDim.x + threadIdx.x;
    if (i >= E) return;
    int s, d;
    if (g_is64) {
        const long long* p = (const long long*)ei;
        s = (int)p[i];
        d = (int)p[(size_t)E + i];
    } else {
        const int* p = (const int*)ei;
        s = p[i];
        d = p[E + i];
    }
    s = min(max(s, 0), n - 1);
    d = min(max(d, 0), n - 1);
    g_esrc[i] = s;
    g_edst[i] = d;
    atomicAdd(&g_deg[d], 1);
}

__global__ void k_convert_batch(const void* __restrict__ b, int n) {
    int i = blockIdx.x * blockDim.x + threadIdx.x;
    if (i >= n) return;
    int v;
    if (g_is64) v = (int)((const long long*)b)[i];
    else        v = ((const int*)b)[i];
    g_batch[i] = min(max(v, 0), NG - 1);
}

// ---------------- 3-kernel exclusive scan: g_deg -> g_ptr ----------------
__global__ void k_scan1(int n) {
    __shared__ int sh[256];
    int base = blockIdx.x * 2048 + threadIdx.x * 8;
    int s = 0;
#pragma unroll
    for (int k = 0; k < 8; k++) {
        int idx = base + k;
        if (idx < n) s += g_deg[idx];
    }
    sh[threadIdx.x] = s;
    __syncthreads();
    for (int o = 128; o > 0; o >>= 1) {
        if (threadIdx.x < o) sh[threadIdx.x] += sh[threadIdx.x + o];
        __syncthreads();
    }
    if (threadIdx.x == 0) g_part[blockIdx.x] = sh[0];
}

__global__ void k_scan2(int nb, int n) {
    if (threadIdx.x == 0 && blockIdx.x == 0) {
        int run = 0;
        for (int b = 0; b < nb; b++) {
            int t = g_part[b];
            g_part[b] = run;
            run += t;
        }
        g_ptr[n] = run;
    }
}

__global__ void k_scan3(int n) {
    __shared__ int sh[256];
    int base = blockIdx.x * 2048 + threadIdx.x * 8;
    int loc[8];
    int s = 0;
#pragma unroll
    for (int k = 0; k < 8; k++) {
        int idx = base + k;
        loc[k] = s;
        if (idx < n) s += g_deg[idx];
    }
    sh[threadIdx.x] = s;
    __syncthreads();
    for (int o = 1; o < 256; o <<= 1) {
        int t = 0;
        if ((int)threadIdx.x >= o) t = sh[threadIdx.x - o];
        __syncthreads();
        sh[threadIdx.x] += t;
        __syncthreads();
    }
    int off = g_part[blockIdx.x] + sh[threadIdx.x] - s;
#pragma unroll
    for (int k = 0; k < 8; k++) {
        int idx = base + k;
        if (idx < n) {
            g_ptr[idx] = off + loc[k];
            g_deg[idx] = 0;
        }
    }
}

// ---------------- scatter edges (+self loops) into CSR ----------------
__global__ void k_scatter(int E, int n) {
    int i = blockIdx.x * blockDim.x + threadIdx.x;
    int tot = E + n;
    if (i >= tot) return;
    int s, d;
    if (i < E) { s = g_esrc[i]; d = g_edst[i]; }
    else       { s = d = i - E; }
    int p = atomicAdd(&g_deg[d], 1);
    g_src[g_ptr[d] + p] = s;
}

// ---------------- node transform, layer 1 (in-dim 3) ----------------
__global__ void k_transform_in(const float* __restrict__ x, const float* __restrict__ pos,
                               const float* __restrict__ W, const float* __restrict__ asrc,
                               const float* __restrict__ adst, int n) {
    __shared__ float ss[8], sd[8];
    int g = threadIdx.x >> 6;
    int c = threadIdx.x & 63;
    int node = blockIdx.x * 4 + g;
    bool valid = node < n;
    float h = 0.f;
    if (valid) {
        float p0 = pos[node * 2];
        float p1 = pos[node * 2 + 1];
        float xv = x[node];
        h = p0 * W[c] + p1 * W[64 + c] + xv * W[128 + c];
        g_hB16[(size_t)node * DH + c] = __float2half(h);
    }
    float vs = valid ? h * asrc[c] : 0.f;
    float vd = valid ? h * adst[c] : 0.f;
#pragma unroll
    for (int o = 16; o > 0; o >>= 1) {
        vs += __shfl_xor_sync(0xffffffffu, vs, o);
        vd += __shfl_xor_sync(0xffffffffu, vd, o);
    }
    int w = threadIdx.x >> 5;
    if ((threadIdx.x & 31) == 0) { ss[w] = vs; sd[w] = vd; }
    __syncthreads();
    if (valid && (threadIdx.x & 63) == 0) {
        g_as[node] = ss[w] + ss[w + 1];
        g_ad[node] = sd[w] + sd[w + 1];
    }
}

// ---------------- node transform, layers 2/3: g_hA (fp32) -> g_hB16 (fp16) ----------------
__global__ __launch_bounds__(256) void k_transform64(const float* __restrict__ W,
                                                     const float* __restrict__ asrc,
                                                     const float* __restrict__ adst,
                                                     int n, int ntiles) {
    __shared__ float4 sW[DH * 16];
    __shared__ float s_h[TN][DH + 1];
    int tid = threadIdx.x;
    for (int i = tid; i < DH * 16; i += 256) sW[i] = ((const float4*)W)[i];
    int g = tid >> 4;
    int c4 = tid & 15;
    float4 as4 = ((const float4*)asrc)[c4];
    float4 ad4 = ((const float4*)adst)[c4];
    __syncthreads();

    for (int tile = blockIdx.x; tile < ntiles; tile += gridDim.x) {
        int node = tile * TN + g;
        float4 v = (node < n) ? ((const float4*)g_hA)[(size_t)node * 16 + c4]
                              : make_float4(0.f, 0.f, 0.f, 0.f);
        s_h[g][c4 * 4 + 0] = v.x;
        s_h[g][c4 * 4 + 1] = v.y;
        s_h[g][c4 * 4 + 2] = v.z;
        s_h[g][c4 * 4 + 3] = v.w;
        __syncthreads();
        float4 acc = make_float4(0.f, 0.f, 0.f, 0.f);
#pragma unroll
        for (int k = 0; k < DH; k++) {
            float hk = s_h[g][k];
            float4 w4 = sW[k * 16 + c4];
            acc.x += hk * w4.x;
            acc.y += hk * w4.y;
            acc.z += hk * w4.z;
            acc.w += hk * w4.w;
        }
        if (node < n) {
            __half2 lo = __floats2half2_rn(acc.x, acc.y);
            __half2 hi = __floats2half2_rn(acc.z, acc.w);
            uint2 packed;
            packed.x = *reinterpret_cast<unsigned int*>(&lo);
            packed.y = *reinterpret_cast<unsigned int*>(&hi);
            ((uint2*)g_hB16)[(size_t)node * 16 + c4] = packed;
        }
        float vs = acc.x * as4.x + acc.y * as4.y + acc.z * as4.z + acc.w * as4.w;
        float vd = acc.x * ad4.x + acc.y * ad4.y + acc.z * ad4.z + acc.w * ad4.w;
#pragma unroll
        for (int o = 8; o > 0; o >>= 1) {
            vs += __shfl_xor_sync(0xffffffffu, vs, o);
            vd += __shfl_xor_sync(0xffffffffu, vd, o);
        }
        if (node < n && c4 == 0) {
            g_as[node] = vs;
            g_ad[node] = vd;
        }
        __syncthreads();
    }
}

// ---------------- GAT aggregation: warp/node, paired-edge 128B fp16 rows ----------------
__device__ __forceinline__ float lrelu(float t) { return t > 0.f ? t : NEG * t; }

__device__ __forceinline__ void acc_row(float4& acc, uint2 raw, float wt) {
    __half2 p0 = *reinterpret_cast<__half2*>(&raw.x);
    __half2 p1 = *reinterpret_cast<__half2*>(&raw.y);
    float2 f0 = __half22float2(p0);
    float2 f1 = __half22float2(p1);
    acc.x += wt * f0.x;
    acc.y += wt * f0.y;
    acc.z += wt * f1.x;
    acc.w += wt * f1.y;
}

__global__ __launch_bounds__(256) void k_aggregate(const float* __restrict__ bias, int n) {
    int node = blockIdx.x * 8 + (threadIdx.x >> 5);
    if (node >= n) return;
    int lane = threadIdx.x & 31;
    int half = lane >> 4;
    int qc = lane & 15;
    int start = g_ptr[node];
    int end = g_ptr[node + 1];
    int deg = end - start;   // >= 1
    float ad = g_ad[node];
    const uint2* __restrict__ h2 = (const uint2*)g_hB16;
    float4 acc = make_float4(0.f, 0.f, 0.f, 0.f);

    if (deg <= 32) {
        int sv = 0;
        float e = -1e30f;
        if (lane < deg) {
            sv = g_src[start + lane];
            e = lrelu(g_as[sv] + ad);
        }
        float m = e;
#pragma unroll
        for (int o = 16; o > 0; o >>= 1) m = fmaxf(m, __shfl_xor_sync(0xffffffffu, m, o));
        float w = (lane < deg) ? __expf(e - m) : 0.f;
        float s = w;
#pragma unroll
        for (int o = 16; o > 0; o >>= 1) s += __shfl_xor_sync(0xffffffffu, s, o);
        w *= 1.f / (s + 1e-16f);
        for (int t = 0; t < deg; t += 2) {
            int idx = t + half;
            int st = __shfl_sync(0xffffffffu, sv, idx & 31);
            float wt = __shfl_sync(0xffffffffu, w, idx & 31);
            if (idx >= deg) wt = 0.f;
            uint2 raw = h2[(size_t)st * 16 + qc];   // 128B row per 16 lanes
            acc_row(acc, raw, wt);
        }
    } else {
        float m = -1e30f;
        for (int j = start + lane; j < end; j += 32)
            m = fmaxf(m, lrelu(g_as[g_src[j]] + ad));
#pragma unroll
        for (int o = 16; o > 0; o >>= 1) m = fmaxf(m, __shfl_xor_sync(0xffffffffu, m, o));
        float s = 0.f;
        for (int j = start + lane; j < end; j += 32)
            s += __expf(lrelu(g_as[g_src[j]] + ad) - m);
#pragma unroll
        for (int o = 16; o > 0; o >>= 1) s += __shfl_xor_sync(0xffffffffu, s, o);
        float invs = 1.f / (s + 1e-16f);
        for (int base = start; base < end; base += 32) {
            int cnt = min(32, end - base);
            int sv = 0;
            float w = 0.f;
            if (lane < cnt) {
                sv = g_src[base + lane];
                w = __expf(lrelu(g_as[sv] + ad) - m) * invs;
            }
            for (int t = 0; t < cnt; t += 2) {
                int idx = t + half;
                int st = __shfl_sync(0xffffffffu, sv, idx & 31);
                float wt = __shfl_sync(0xffffffffu, w, idx & 31);
                if (idx >= cnt) wt = 0.f;
                uint2 raw = h2[(size_t)st * 16 + qc];
                acc_row(acc, raw, wt);
            }
        }
    }
    acc.x += __shfl_xor_sync(0xffffffffu, acc.x, 16);
    acc.y += __shfl_xor_sync(0xffffffffu, acc.y, 16);
    acc.z += __shfl_xor_sync(0xffffffffu, acc.z, 16);
    acc.w += __shfl_xor_sync(0xffffffffu, acc.w, 16);
    if (half == 0) {
        float4 bb = ((const float4*)bias)[qc];
        ((float4*)g_hA)[(size_t)node * 16 + qc] =
            make_float4(acc.x + bb.x, acc.y + bb.y, acc.z + bb.z, acc.w + bb.w);
    }
}

// ---------------- pooling (sorted batch, run-length pre-aggregation) ----------------
__global__ void k_pool(int n) {
    int c = threadIdx.x & 63;
    int chunk = blockIdx.x * 4 + (threadIdx.x >> 6);
    int i0 = chunk * 64;
    if (i0 >= n) return;
    int iend = min(i0 + 64, n);
    float acc = 0.f;
    int cacc = 0;
    int cur = g_batch[i0];
    for (int i = i0; i < iend; i++) {
        int b = g_batch[i];
        if (b != cur) {
            atomicAdd(&g_pool[cur * DH + c], acc);
            if (c == 0) atomicAdd(&g_cnt[cur], cacc);
            acc = 0.f; cacc = 0; cur = b;
        }
        acc += g_hA[(size_t)i * DH + c];
        cacc++;
    }
    atomicAdd(&g_pool[cur * DH + c], acc);
    if (c == 0) atomicAdd(&g_cnt[cur], cacc);
}

// ---------------- classifier head ----------------
__global__ void k_final(const float* __restrict__ Wl, const float* __restrict__ bl,
                        float* __restrict__ out) {
    int t = blockIdx.x * blockDim.x + threadIdx.x;
    if (t >= NG * NC) return;
    int g = t / NC;
    int cls = t % NC;
    float invc = 1.f / fmaxf((float)g_cnt[g], 1.f);
    float dot = 0.f;
#pragma unroll
    for (int d = 0; d < DH; d++) dot += g_pool[g * DH + d] * Wl[d * NC + cls];
    out[t] = dot * invc + bl[cls];
}

// ---------------- host launcher ----------------
extern "C" void kernel_launch(void* const* d_in, const int* in_sizes, int n_in,
                              void* d_out, int out_size) {
    const float* x = (const float*)d_in[0];
    const float* pos = (const float*)d_in[1];
    const void* ei = d_in[2];
    const void* batch = d_in[3];
    const float* W1 = (const float*)d_in[4];
    const float* as1 = (const float*)d_in[5];
    const float* ad1 = (const float*)d_in[6];
    const float* b1 = (const float*)d_in[7];
    const float* W2 = (const float*)d_in[8];
    const float* as2 = (const float*)d_in[9];
    const float* ad2 = (const float*)d_in[10];
    const float* b2 = (const float*)d_in[11];
    const float* W3 = (const float*)d_in[12];
    const float* as3 = (const float*)d_in[13];
    const float* ad3 = (const float*)d_in[14];
    const float* b3 = (const float*)d_in[15];
    const float* Wl = (const float*)d_in[16];
    const float* bl = (const float*)d_in[17];
    float* out = (float*)d_out;

    int n = in_sizes[0];
    int E = in_sizes[2] / 2;
    int nb = (n + 2047) / 2048;
    int ntiles = (n + TN - 1) / TN;

    k_detect<<<1, 256>>>((const unsigned int*)ei, E);
    int initT = n;
    if (initT < NG * DH) initT = NG * DH;
    k_init<<<(initT + 255) / 256, 256>>>(n);
    k_convert_edges<<<(E + 255) / 256, 256>>>(ei, E, n);
    k_convert_batch<<<(n + 255) / 256, 256>>>(batch, n);

    k_scan1<<<nb, 256>>>(n);
    k_scan2<<<1, 32>>>(nb, n);
    k_scan3<<<nb, 256>>>(n);
    k_scatter<<<(E + n + 255) / 256, 256>>>(E, n);

    int tb = (n + 3) / 4;
    int ab = (n + 7) / 8;
    int tg = 1184;

    k_transform_in<<<tb, 256>>>(x, pos, W1, as1, ad1, n);
    k_aggregate<<<ab, 256>>>(b1, n);
    k_transform64<<<tg, 256>>>(W2, as2, ad2, n, ntiles);
    k_aggregate<<<ab, 256>>>(b2, n);
    k_transform64<<<tg, 256>>>(W3, as3, ad3, n, ntiles);
    k_aggregate<<<ab, 256>>>(b3, n);

    int chunks = (n + 63) / 64;
    k_pool<<<(chunks + 3) / 4, 256>>>(n);
    k_final<<<(NG * NC + 255) / 256, 256>>>(Wl, bl, out);
}

// round 9
// speedup vs baseline: 1.2665x; 1.0442x over previous
#include <cuda_runtime.h>
#include <cuda_fp16.h>
#include <math.h>

#define MAXN 100000
#define MAXE 1600000
#define MAXET (MAXE + MAXN)
#define DH 64
#define NG 128
#define NC 10
#define NEG 0.2f
#define TN 16   // nodes per transform tile

// ---------------- static device scratch ----------------
__device__ int   g_is64;
__device__ int   g_esrc[MAXE];
__device__ int   g_edst[MAXE];
__device__ int   g_batch[MAXN];
__device__ int   g_deg[MAXN];
__device__ int   g_ptr[MAXN + 1];
__device__ int   g_src[MAXET];
__device__ __align__(16) float  g_hA[MAXN * DH];      // fp32 layer output
__device__ __align__(16) __half g_hB16[MAXN * DH];    // fp16 gather operand (128B rows)
__device__ float g_as[MAXN];
__device__ float g_ad[MAXN];
__device__ __align__(16) float g_pool[NG * DH];
__device__ int   g_cnt[NG];
__device__ int   g_part[64];

// ---------------- dtype detection: int64 (odd 32-bit words all zero) vs int32 ----------------
__global__ void k_detect(const unsigned int* __restrict__ w, int E) {
    __shared__ int nz;
    if (threadIdx.x == 0) nz = 0;
    __syncthreads();
    for (int k = threadIdx.x; k < 1024; k += blockDim.x) {
        long long pos = 2ll * ((long long)k * (E - 1) / 1024) + 1;
        if (w[pos] != 0u) atomicAdd(&nz, 1);
    }
    __syncthreads();
    if (threadIdx.x == 0) g_is64 = (nz == 0) ? 1 : 0;
}

// ---------------- init ----------------
__global__ void k_init(int n) {
    int i = blockIdx.x * blockDim.x + threadIdx.x;
    if (i < n) g_deg[i] = 1;    // self loop pre-counted
    if (i < NG * DH) g_pool[i] = 0.f;
    if (i < NG) g_cnt[i] = 0;
}

// ---------------- convert edges to int32 (clamped) + fused degree count ----------------
__global__ void k_convert_edges(const void* __restrict__ ei, int E, int n) {
    int i = blockIdx.x * blockDim.x + threadIdx.x;
    if (i >= E) return;
    int s, d;
    if (g_is64) {
        const long long* p = (const long long*)ei;
        s = (int)p[i];
        d = (int)p[(size_t)E + i];
    } else {
        const int* p = (const int*)ei;
        s = p[i];
        d = p[E + i];
    }
    s = min(max(s, 0), n - 1);
    d = min(max(d, 0), n - 1);
    g_esrc[i] = s;
    g_edst[i] = d;
    atomicAdd(&g_deg[d], 1);
}

__global__ void k_convert_batch(const void* __restrict__ b, int n) {
    int i = blockIdx.x * blockDim.x + threadIdx.x;
    if (i >= n) return;
    int v;
    if (g_is64) v = (int)((const long long*)b)[i];
    else        v = ((const int*)b)[i];
    g_batch[i] = min(max(v, 0), NG - 1);
}

// ---------------- 3-kernel exclusive scan: g_deg -> g_ptr ----------------
__global__ void k_scan1(int n) {
    __shared__ int sh[256];
    int base = blockIdx.x * 2048 + threadIdx.x * 8;
    int s = 0;
#pragma unroll
    for (int k = 0; k < 8; k++) {
        int idx = base + k;
        if (idx < n) s += g_deg[idx];
    }
    sh[threadIdx.x] = s;
    __syncthreads();
    for (int o = 128; o > 0; o >>= 1) {
        if (threadIdx.x < o) sh[threadIdx.x] += sh[threadIdx.x + o];
        __syncthreads();
    }
    if (threadIdx.x == 0) g_part[blockIdx.x] = sh[0];
}

__global__ void k_scan2(int nb, int n) {
    if (threadIdx.x == 0 && blockIdx.x == 0) {
        int run = 0;
        for (int b = 0; b < nb; b++) {
            int t = g_part[b];
            g_part[b] = run;
            run += t;
        }
        g_ptr[n] = run;
    }
}

__global__ void k_scan3(int n) {
    __shared__ int sh[256];
    int base = blockIdx.x * 2048 + threadIdx.x * 8;
    int loc[8];
    int s = 0;
#pragma unroll
    for (int k = 0; k < 8; k++) {
        int idx = base + k;
        loc[k] = s;
        if (idx < n) s += g_deg[idx];
    }
    sh[threadIdx.x] = s;
    __syncthreads();
    for (int o = 1; o < 256; o <<= 1) {
        int t = 0;
        if ((int)threadIdx.x >= o) t = sh[threadIdx.x - o];
        __syncthreads();
        sh[threadIdx.x] += t;
        __syncthreads();
    }
    int off = g_part[blockIdx.x] + sh[threadIdx.x] - s;
#pragma unroll
    for (int k = 0; k < 8; k++) {
        int idx = base + k;
        if (idx < n) {
            g_ptr[idx] = off + loc[k];
            g_deg[idx] = 0;
        }
    }
}

// ---------------- scatter edges (+self loops) into CSR ----------------
__global__ void k_scatter(int E, int n) {
    int i = blockIdx.x * blockDim.x + threadIdx.x;
    int tot = E + n;
    if (i >= tot) return;
    int s, d;
    if (i < E) { s = g_esrc[i]; d = g_edst[i]; }
    else       { s = d = i - E; }
    int p = atomicAdd(&g_deg[d], 1);
    g_src[g_ptr[d] + p] = s;
}

// ---------------- node transform, layer 1 (in-dim 3) ----------------
__global__ void k_transform_in(const float* __restrict__ x, const float* __restrict__ pos,
                               const float* __restrict__ W, const float* __restrict__ asrc,
                               const float* __restrict__ adst, int n) {
    __shared__ float ss[8], sd[8];
    int g = threadIdx.x >> 6;
    int c = threadIdx.x & 63;
    int node = blockIdx.x * 4 + g;
    bool valid = node < n;
    float h = 0.f;
    if (valid) {
        float p0 = pos[node * 2];
        float p1 = pos[node * 2 + 1];
        float xv = x[node];
        h = p0 * W[c] + p1 * W[64 + c] + xv * W[128 + c];
        g_hB16[(size_t)node * DH + c] = __float2half(h);
    }
    float vs = valid ? h * asrc[c] : 0.f;
    float vd = valid ? h * adst[c] : 0.f;
#pragma unroll
    for (int o = 16; o > 0; o >>= 1) {
        vs += __shfl_xor_sync(0xffffffffu, vs, o);
        vd += __shfl_xor_sync(0xffffffffu, vd, o);
    }
    int w = threadIdx.x >> 5;
    if ((threadIdx.x & 31) == 0) { ss[w] = vs; sd[w] = vd; }
    __syncthreads();
    if (valid && (threadIdx.x & 63) == 0) {
        g_as[node] = ss[w] + ss[w + 1];
        g_ad[node] = sd[w] + sd[w + 1];
    }
}

// ---------------- node transform, layers 2/3: g_hA (fp32) -> g_hB16 (fp16) ----------------
__global__ __launch_bounds__(256) void k_transform64(const float* __restrict__ W,
                                                     const float* __restrict__ asrc,
                                                     const float* __restrict__ adst,
                                                     int n, int ntiles) {
    __shared__ float4 sW[DH * 16];
    __shared__ float s_h[TN][DH + 1];
    int tid = threadIdx.x;
    for (int i = tid; i < DH * 16; i += 256) sW[i] = ((const float4*)W)[i];
    int g = tid >> 4;
    int c4 = tid & 15;
    float4 as4 = ((const float4*)asrc)[c4];
    float4 ad4 = ((const float4*)adst)[c4];
    __syncthreads();

    for (int tile = blockIdx.x; tile < ntiles; tile += gridDim.x) {
        int node = tile * TN + g;
        float4 v = (node < n) ? ((const float4*)g_hA)[(size_t)node * 16 + c4]
                              : make_float4(0.f, 0.f, 0.f, 0.f);
        s_h[g][c4 * 4 + 0] = v.x;
        s_h[g][c4 * 4 + 1] = v.y;
        s_h[g][c4 * 4 + 2] = v.z;
        s_h[g][c4 * 4 + 3] = v.w;
        __syncthreads();
        float4 acc = make_float4(0.f, 0.f, 0.f, 0.f);
#pragma unroll
        for (int k = 0; k < DH; k++) {
            float hk = s_h[g][k];
            float4 w4 = sW[k * 16 + c4];
            acc.x += hk * w4.x;
            acc.y += hk * w4.y;
            acc.z += hk * w4.z;
            acc.w += hk * w4.w;
        }
        if (node < n) {
            __half2 lo = __floats2half2_rn(acc.x, acc.y);
            __half2 hi = __floats2half2_rn(acc.z, acc.w);
            uint2 packed;
            packed.x = *reinterpret_cast<unsigned int*>(&lo);
            packed.y = *reinterpret_cast<unsigned int*>(&hi);
            ((uint2*)g_hB16)[(size_t)node * 16 + c4] = packed;
        }
        float vs = acc.x * as4.x + acc.y * as4.y + acc.z * as4.z + acc.w * as4.w;
        float vd = acc.x * ad4.x + acc.y * ad4.y + acc.z * ad4.z + acc.w * ad4.w;
#pragma unroll
        for (int o = 8; o > 0; o >>= 1) {
            vs += __shfl_xor_sync(0xffffffffu, vs, o);
            vd += __shfl_xor_sync(0xffffffffu, vd, o);
        }
        if (node < n && c4 == 0) {
            g_as[node] = vs;
            g_ad[node] = vd;
        }
        __syncthreads();
    }
}

// ---------------- GAT aggregation: warp/node, no max-sub, pipelined gather ----------------
__device__ __forceinline__ float lrelu(float t) { return t > 0.f ? t : NEG * t; }

__device__ __forceinline__ void acc_row(float4& acc, uint2 raw, float wt) {
    __half2 p0 = *reinterpret_cast<__half2*>(&raw.x);
    __half2 p1 = *reinterpret_cast<__half2*>(&raw.y);
    float2 f0 = __half22float2(p0);
    float2 f1 = __half22float2(p1);
    acc.x += wt * f0.x;
    acc.y += wt * f0.y;
    acc.z += wt * f1.x;
    acc.w += wt * f1.y;
}

__global__ __launch_bounds__(256) void k_aggregate(const float* __restrict__ bias, int n) {
    int node = blockIdx.x * 8 + (threadIdx.x >> 5);
    if (node >= n) return;
    int lane = threadIdx.x & 31;
    int half = lane >> 4;
    int qc = lane & 15;
    int start = g_ptr[node];
    int end = g_ptr[node + 1];
    int deg = end - start;   // >= 1
    float ad = g_ad[node];
    const uint2* __restrict__ h2 = (const uint2*)g_hB16;
    float4 acc = make_float4(0.f, 0.f, 0.f, 0.f);

    if (deg <= 32) {
        int sv = 0;
        float w = 0.f;
        if (lane < deg) {
            sv = g_src[start + lane];
            w = __expf(lrelu(g_as[sv] + ad));   // no max-sub: |e| << 88
        }
        float s = w;
#pragma unroll
        for (int o = 16; o > 0; o >>= 1) s += __shfl_xor_sync(0xffffffffu, s, o);
        w *= 1.f / (s + 1e-16f);
        // software-pipelined: next pair's shfl+load issued before consuming current
        int idx = half;
        int st = __shfl_sync(0xffffffffu, sv, idx);
        float wt = __shfl_sync(0xffffffffu, w, idx);
        if (idx >= deg) wt = 0.f;
        uint2 raw = h2[(size_t)st * 16 + qc];
        for (int t = 2; t < deg; t += 2) {
            int idx2 = t + half;
            int st2 = __shfl_sync(0xffffffffu, sv, idx2 & 31);
            float wt2 = __shfl_sync(0xffffffffu, w, idx2 & 31);
            if (idx2 >= deg) wt2 = 0.f;
            uint2 raw2 = h2[(size_t)st2 * 16 + qc];
            acc_row(acc, raw, wt);
            raw = raw2;
            wt = wt2;
        }
        acc_row(acc, raw, wt);
    } else {
        // pass 1: denominator (no max-sub)
        float s = 0.f;
        for (int j = start + lane; j < end; j += 32)
            s += __expf(lrelu(g_as[g_src[j]] + ad));
#pragma unroll
        for (int o = 16; o > 0; o >>= 1) s += __shfl_xor_sync(0xffffffffu, s, o);
        float invs = 1.f / (s + 1e-16f);
        // pass 2: weighted gather, pipelined within each 32-edge chunk
        for (int base = start; base < end; base += 32) {
            int cnt = min(32, end - base);
            int sv = 0;
            float w = 0.f;
            if (lane < cnt) {
                sv = g_src[base + lane];
                w = __expf(lrelu(g_as[sv] + ad)) * invs;
            }
            int idx = half;
            int st = __shfl_sync(0xffffffffu, sv, idx);
            float wt = __shfl_sync(0xffffffffu, w, idx);
            if (idx >= cnt) wt = 0.f;
            uint2 raw = h2[(size_t)st * 16 + qc];
            for (int t = 2; t < cnt; t += 2) {
                int idx2 = t + half;
                int st2 = __shfl_sync(0xffffffffu, sv, idx2 & 31);
                float wt2 = __shfl_sync(0xffffffffu, w, idx2 & 31);
                if (idx2 >= cnt) wt2 = 0.f;
                uint2 raw2 = h2[(size_t)st2 * 16 + qc];
                acc_row(acc, raw, wt);
                raw = raw2;
                wt = wt2;
            }
            acc_row(acc, raw, wt);
        }
    }
    acc.x += __shfl_xor_sync(0xffffffffu, acc.x, 16);
    acc.y += __shfl_xor_sync(0xffffffffu, acc.y, 16);
    acc.z += __shfl_xor_sync(0xffffffffu, acc.z, 16);
    acc.w += __shfl_xor_sync(0xffffffffu, acc.w, 16);
    if (half == 0) {
        float4 bb = ((const float4*)bias)[qc];
        ((float4*)g_hA)[(size_t)node * 16 + qc] =
            make_float4(acc.x + bb.x, acc.y + bb.y, acc.z + bb.z, acc.w + bb.w);
    }
}

// ---------------- pooling (sorted batch, run-length pre-aggregation) ----------------
__global__ void k_pool(int n) {
    int c = threadIdx.x & 63;
    int chunk = blockIdx.x * 4 + (threadIdx.x >> 6);
    int i0 = chunk * 64;
    if (i0 >= n) return;
    int iend = min(i0 + 64, n);
    float acc = 0.f;
    int cacc = 0;
    int cur = g_batch[i0];
    for (int i = i0; i < iend; i++) {
        int b = g_batch[i];
        if (b != cur) {
            atomicAdd(&g_pool[cur * DH + c], acc);
            if (c == 0) atomicAdd(&g_cnt[cur], cacc);
            acc = 0.f; cacc = 0; cur = b;
        }
        acc += g_hA[(size_t)i * DH + c];
        cacc++;
    }
    atomicAdd(&g_pool[cur * DH + c], acc);
    if (c == 0) atomicAdd(&g_cnt[cur], cacc);
}

// ---------------- classifier head ----------------
__global__ void k_final(const float* __restrict__ Wl, const float* __restrict__ bl,
                        float* __restrict__ out) {
    int t = blockIdx.x * blockDim.x + threadIdx.x;
    if (t >= NG * NC) return;
    int g = t / NC;
    int cls = t % NC;
    float invc = 1.f / fmaxf((float)g_cnt[g], 1.f);
    float dot = 0.f;
#pragma unroll
    for (int d = 0; d < DH; d++) dot += g_pool[g * DH + d] * Wl[d * NC + cls];
    out[t] = dot * invc + bl[cls];
}

// ---------------- host launcher ----------------
extern "C" void kernel_launch(void* const* d_in, const int* in_sizes, int n_in,
                              void* d_out, int out_size) {
    const float* x = (const float*)d_in[0];
    const float* pos = (const float*)d_in[1];
    const void* ei = d_in[2];
    const void* batch = d_in[3];
    const float* W1 = (const float*)d_in[4];
    const float* as1 = (const float*)d_in[5];
    const float* ad1 = (const float*)d_in[6];
    const float* b1 = (const float*)d_in[7];
    const float* W2 = (const float*)d_in[8];
    const float* as2 = (const float*)d_in[9];
    const float* ad2 = (const float*)d_in[10];
    const float* b2 = (const float*)d_in[11];
    const float* W3 = (const float*)d_in[12];
    const float* as3 = (const float*)d_in[13];
    const float* ad3 = (const float*)d_in[14];
    const float* b3 = (const float*)d_in[15];
    const float* Wl = (const float*)d_in[16];
    const float* bl = (const float*)d_in[17];
    float* out = (float*)d_out;

    int n = in_sizes[0];
    int E = in_sizes[2] / 2;
    int nb = (n + 2047) / 2048;
    int ntiles = (n + TN - 1) / TN;

    k_detect<<<1, 256>>>((const unsigned int*)ei, E);
    int initT = n;
    if (initT < NG * DH) initT = NG * DH;
    k_init<<<(initT + 255) / 256, 256>>>(n);
    k_convert_edges<<<(E + 255) / 256, 256>>>(ei, E, n);
    k_convert_batch<<<(n + 255) / 256, 256>>>(batch, n);

    k_scan1<<<nb, 256>>>(n);
    k_scan2<<<1, 32>>>(nb, n);
    k_scan3<<<nb, 256>>>(n);
    k_scatter<<<(E + n + 255) / 256, 256>>>(E, n);

    int tb = (n + 3) / 4;
    int ab = (n + 7) / 8;
    int tg = 1184;

    k_transform_in<<<tb, 256>>>(x, pos, W1, as1, ad1, n);
    k_aggregate<<<ab, 256>>>(b1, n);
    k_transform64<<<tg, 256>>>(W2, as2, ad2, n, ntiles);
    k_aggregate<<<ab, 256>>>(b2, n);
    k_transform64<<<tg, 256>>>(W3, as3, ad3, n, ntiles);
    k_aggregate<<<ab, 256>>>(b3, n);

    int chunks = (n + 63) / 64;
    k_pool<<<(chunks + 3) / 4, 256>>>(n);
    k_final<<<(NG * NC + 255) / 256, 256>>>(Wl, bl, out);
}

// round 11
// speedup vs baseline: 1.2724x; 1.0046x over previous
#include <cuda_runtime.h>
#include <cuda_fp16.h>
#include <math.h>

#define MAXN 100000
#define MAXE 1600000
#define MAXET (MAXE + MAXN)
#define DH 64
#define NG 128
#define NC 10
#define NEG 0.2f

// ---------------- static device scratch ----------------
__device__ int   g_is64;
__device__ int   g_esrc[MAXE];
__device__ int   g_edst[MAXE];
__device__ int   g_batch[MAXN];
__device__ int   g_deg[MAXN];
__device__ int   g_ptr[MAXN + 1];
__device__ int   g_src[MAXET];
__device__ __align__(16) __half g_h16A[MAXN * DH];   // fp16 feature ping
__device__ __align__(16) __half g_h16B[MAXN * DH];   // fp16 feature pong
__device__ __align__(16) float  g_hA[MAXN * DH];     // fp32 final-layer output (pooling)
__device__ float g_asA[MAXN], g_adA[MAXN];
__device__ float g_asB[MAXN], g_adB[MAXN];
__device__ __align__(16) float g_pool[NG * DH];
__device__ int   g_cnt[NG];
__device__ int   g_part[64];

// ---------------- dtype detection: int64 (odd 32-bit words all zero) vs int32 ----------------
__global__ void k_detect(const unsigned int* __restrict__ w, int E) {
    __shared__ int nz;
    if (threadIdx.x == 0) nz = 0;
    __syncthreads();
    for (int k = threadIdx.x; k < 1024; k += blockDim.x) {
        long long pos = 2ll * ((long long)k * (E - 1) / 1024) + 1;
        if (w[pos] != 0u) atomicAdd(&nz, 1);
    }
    __syncthreads();
    if (threadIdx.x == 0) g_is64 = (nz == 0) ? 1 : 0;
}

// ---------------- init ----------------
__global__ void k_init(int n) {
    int i = blockIdx.x * blockDim.x + threadIdx.x;
    if (i < n) g_deg[i] = 1;    // self loop pre-counted
    if (i < NG * DH) g_pool[i] = 0.f;
    if (i < NG) g_cnt[i] = 0;
}

// ---------------- convert edges to int32 (clamped) + fused degree count ----------------
__global__ void k_convert_edges(const void* __restrict__ ei, int E, int n) {
    int i = blockIdx.x * blockDim.x + threadIdx.x;
    if (i >= E) return;
    int s, d;
    if (g_is64) {
        const long long* p = (const long long*)ei;
        s = (int)p[i];
        d = (int)p[(size_t)E + i];
    } else {
        const int* p = (const int*)ei;
        s = p[i];
        d = p[E + i];
    }
    s = min(max(s, 0), n - 1);
    d = min(max(d, 0), n - 1);
    g_esrc[i] = s;
    g_edst[i] = d;
    atomicAdd(&g_deg[d], 1);
}

__global__ void k_convert_batch(const void* __restrict__ b, int n) {
    int i = blockIdx.x * blockDim.x + threadIdx.x;
    if (i >= n) return;
    int v;
    if (g_is64) v = (int)((const long long*)b)[i];
    else        v = ((const int*)b)[i];
    g_batch[i] = min(max(v, 0), NG - 1);
}

// ---------------- 3-kernel exclusive scan: g_deg -> g_ptr ----------------
__global__ void k_scan1(int n) {
    __shared__ int sh[256];
    int base = blockIdx.x * 2048 + threadIdx.x * 8;
    int s = 0;
#pragma unroll
    for (int k = 0; k < 8; k++) {
        int idx = base + k;
        if (idx < n) s += g_deg[idx];
    }
    sh[threadIdx.x] = s;
    __syncthreads();
    for (int o = 128; o > 0; o >>= 1) {
        if (threadIdx.x < o) sh[threadIdx.x] += sh[threadIdx.x + o];
        __syncthreads();
    }
    if (threadIdx.x == 0) g_part[blockIdx.x] = sh[0];
}

__global__ void k_scan2(int nb, int n) {
    if (threadIdx.x == 0 && blockIdx.x == 0) {
        int run = 0;
        for (int b = 0; b < nb; b++) {
            int t = g_part[b];
            g_part[b] = run;
            run += t;
        }
        g_ptr[n] = run;
    }
}

__global__ void k_scan3(int n) {
    __shared__ int sh[256];
    int base = blockIdx.x * 2048 + threadIdx.x * 8;
    int loc[8];
    int s = 0;
#pragma unroll
    for (int k = 0; k < 8; k++) {
        int idx = base + k;
        loc[k] = s;
        if (idx < n) s += g_deg[idx];
    }
    sh[threadIdx.x] = s;
    __syncthreads();
    for (int o = 1; o < 256; o <<= 1) {
        int t = 0;
        if ((int)threadIdx.x >= o) t = sh[threadIdx.x - o];
        __syncthreads();
        sh[threadIdx.x] += t;
        __syncthreads();
    }
    int off = g_part[blockIdx.x] + sh[threadIdx.x] - s;
#pragma unroll
    for (int k = 0; k < 8; k++) {
        int idx = base + k;
        if (idx < n) {
            g_ptr[idx] = off + loc[k];
            g_deg[idx] = 0;
        }
    }
}

// ---------------- scatter edges (+self loops) into CSR ----------------
__global__ void k_scatter(int E, int n) {
    int i = blockIdx.x * blockDim.x + threadIdx.x;
    int tot = E + n;
    if (i >= tot) return;
    int s, d;
    if (i < E) { s = g_esrc[i]; d = g_edst[i]; }
    else       { s = d = i - E; }
    int p = atomicAdd(&g_deg[d], 1);
    g_src[g_ptr[d] + p] = s;
}

// ---------------- node transform, layer 1 (in-dim 3) -> g_h16A + asA/adA ----------------
__global__ void k_transform_in(const float* __restrict__ x, const float* __restrict__ pos,
                               const float* __restrict__ W, const float* __restrict__ asrc,
                               const float* __restrict__ adst, int n) {
    __shared__ float ss[8], sd[8];
    int g = threadIdx.x >> 6;
    int c = threadIdx.x & 63;
    int node = blockIdx.x * 4 + g;
    bool valid = node < n;
    float h = 0.f;
    if (valid) {
        float p0 = pos[node * 2];
        float p1 = pos[node * 2 + 1];
        float xv = x[node];
        h = p0 * W[c] + p1 * W[64 + c] + xv * W[128 + c];
        g_h16A[(size_t)node * DH + c] = __float2half(h);
    }
    float vs = valid ? h * asrc[c] : 0.f;
    float vd = valid ? h * adst[c] : 0.f;
#pragma unroll
    for (int o = 16; o > 0; o >>= 1) {
        vs += __shfl_xor_sync(0xffffffffu, vs, o);
        vd += __shfl_xor_sync(0xffffffffu, vd, o);
    }
    int w = threadIdx.x >> 5;
    if ((threadIdx.x & 31) == 0) { ss[w] = vs; sd[w] = vd; }
    __syncthreads();
    if (valid && (threadIdx.x & 63) == 0) {
        g_asA[node] = ss[w] + ss[w + 1];
        g_adA[node] = sd[w] + sd[w + 1];
    }
}

// ---------------- fused GAT aggregate (+ next-layer transform) ----------------
// mode 0: aggregate layer L, add bias, transform by W_next, emit fp16 + as/ad (ping-pong)
// mode 1: aggregate final layer, add bias, emit fp32 g_hA for pooling
__device__ __forceinline__ float lrelu(float t) { return t > 0.f ? t : NEG * t; }

__device__ __forceinline__ void acc_row(float4& acc, uint2 raw, float wt) {
    __half2 p0 = *reinterpret_cast<__half2*>(&raw.x);
    __half2 p1 = *reinterpret_cast<__half2*>(&raw.y);
    float2 f0 = __half22float2(p0);
    float2 f1 = __half22float2(p1);
    acc.x += wt * f0.x;
    acc.y += wt * f0.y;
    acc.z += wt * f1.x;
    acc.w += wt * f1.y;
}

__global__ __launch_bounds__(256) void k_agg_tr(
    int pp,                              // 0: read A write B; 1: read B write A
    int mode,                            // 0: fused transform; 1: final
    const float* __restrict__ bias,      // current layer bias
    const float* __restrict__ Wn,        // next-layer W (64x64), mode 0
    const float* __restrict__ asn,       // next-layer a_src
    const float* __restrict__ adn,       // next-layer a_dst
    int n, int nblocks)
{
    __shared__ float2 sW[DH * 32];       // sW[k*32+lane] = W[k][2lane..2lane+1]
    __shared__ float sRow[8][DH];
    const __half* hin  = pp ? g_h16B : g_h16A;
    __half*       hout = pp ? g_h16A : g_h16B;
    const float*  as_c = pp ? g_asB : g_asA;
    const float*  ad_c = pp ? g_adB : g_adA;
    float*        as_n = pp ? g_asA : g_asB;
    float*        ad_n = pp ? g_adA : g_adB;

    int tid = threadIdx.x;
    if (mode == 0) {
        for (int i = tid; i < DH * 32; i += 256) sW[i] = ((const float2*)Wn)[i];
        __syncthreads();
    }
    int wid = tid >> 5;
    int lane = tid & 31;
    int half = lane >> 4;
    int qc = lane & 15;
    float2 an2 = make_float2(0.f, 0.f), dn2 = make_float2(0.f, 0.f);
    if (mode == 0) {
        an2 = ((const float2*)asn)[lane];
        dn2 = ((const float2*)adn)[lane];
    }
    const uint2* __restrict__ h2 = (const uint2*)hin;
    float4 bb = ((const float4*)bias)[qc];

    for (int blk = blockIdx.x; blk < nblocks; blk += gridDim.x) {
        int node = blk * 8 + wid;
        if (node < n) {
            int start = g_ptr[node];
            int end = g_ptr[node + 1];
            int deg = end - start;   // >= 1
            float ad = ad_c[node];
            float4 acc = make_float4(0.f, 0.f, 0.f, 0.f);

            if (deg <= 32) {
                int sv = 0;
                float w = 0.f;
                if (lane < deg) {
                    sv = g_src[start + lane];
                    w = __expf(lrelu(as_c[sv] + ad));   // no max-sub: |e| << 88
                }
                float s = w;
#pragma unroll
                for (int o = 16; o > 0; o >>= 1) s += __shfl_xor_sync(0xffffffffu, s, o);
                w *= 1.f / (s + 1e-16f);
                int idx = half;
                int st = __shfl_sync(0xffffffffu, sv, idx);
                float wt = __shfl_sync(0xffffffffu, w, idx);
                if (idx >= deg) wt = 0.f;
                uint2 raw = h2[(size_t)st * 16 + qc];
                for (int t = 2; t < deg; t += 2) {
                    int idx2 = t + half;
                    int st2 = __shfl_sync(0xffffffffu, sv, idx2 & 31);
                    float wt2 = __shfl_sync(0xffffffffu, w, idx2 & 31);
                    if (idx2 >= deg) wt2 = 0.f;
                    uint2 raw2 = h2[(size_t)st2 * 16 + qc];
                    acc_row(acc, raw, wt);
                    raw = raw2;
                    wt = wt2;
                }
                acc_row(acc, raw, wt);
            } else {
                float s = 0.f;
                for (int j = start + lane; j < end; j += 32)
                    s += __expf(lrelu(as_c[g_src[j]] + ad));
#pragma unroll
                for (int o = 16; o > 0; o >>= 1) s += __shfl_xor_sync(0xffffffffu, s, o);
                float invs = 1.f / (s + 1e-16f);
                for (int base = start; base < end; base += 32) {
                    int cnt = min(32, end - base);
                    int sv = 0;
                    float w = 0.f;
                    if (lane < cnt) {
                        sv = g_src[base + lane];
                        w = __expf(lrelu(as_c[sv] + ad)) * invs;
                    }
                    int idx = half;
                    int st = __shfl_sync(0xffffffffu, sv, idx);
                    float wt = __shfl_sync(0xffffffffu, w, idx);
                    if (idx >= cnt) wt = 0.f;
                    uint2 raw = h2[(size_t)st * 16 + qc];
                    for (int t = 2; t < cnt; t += 2) {
                        int idx2 = t + half;
                        int st2 = __shfl_sync(0xffffffffu, sv, idx2 & 31);
                        float wt2 = __shfl_sync(0xffffffffu, w, idx2 & 31);
                        if (idx2 >= cnt) wt2 = 0.f;
                        uint2 raw2 = h2[(size_t)st2 * 16 + qc];
                        acc_row(acc, raw, wt);
                        raw = raw2;
                        wt = wt2;
                    }
                    acc_row(acc, raw, wt);
                }
            }
            // combine halves (all lanes end with full sum)
            acc.x += __shfl_xor_sync(0xffffffffu, acc.x, 16);
            acc.y += __shfl_xor_sync(0xffffffffu, acc.y, 16);
            acc.z += __shfl_xor_sync(0xffffffffu, acc.z, 16);
            acc.w += __shfl_xor_sync(0xffffffffu, acc.w, 16);
            acc.x += bb.x; acc.y += bb.y; acc.z += bb.z; acc.w += bb.w;

            if (mode == 1) {
                if (half == 0)
                    ((float4*)g_hA)[(size_t)node * 16 + qc] = acc;
            } else {
                if (half == 0) {
                    sRow[wid][qc * 4 + 0] = acc.x;
                    sRow[wid][qc * 4 + 1] = acc.y;
                    sRow[wid][qc * 4 + 2] = acc.z;
                    sRow[wid][qc * 4 + 3] = acc.w;
                }
                __syncwarp();
                float o0 = 0.f, o1 = 0.f;
#pragma unroll
                for (int k = 0; k < DH; k++) {
                    float r = sRow[wid][k];
                    float2 w2 = sW[k * 32 + lane];
                    o0 += r * w2.x;
                    o1 += r * w2.y;
                }
                __syncwarp();
                ((__half2*)hout)[(size_t)node * 32 + lane] = __floats2half2_rn(o0, o1);
                float vs = o0 * an2.x + o1 * an2.y;
                float vd = o0 * dn2.x + o1 * dn2.y;
#pragma unroll
                for (int o = 16; o > 0; o >>= 1) {
                    vs += __shfl_xor_sync(0xffffffffu, vs, o);
                    vd += __shfl_xor_sync(0xffffffffu, vd, o);
                }
                if (lane == 0) {
                    as_n[node] = vs;
                    ad_n[node] = vd;
                }
            }
        }
    }
}

// ---------------- pooling (sorted batch, run-length pre-aggregation) ----------------
__global__ void k_pool(int n) {
    int c = threadIdx.x & 63;
    int chunk = blockIdx.x * 4 + (threadIdx.x >> 6);
    int i0 = chunk * 64;
    if (i0 >= n) return;
    int iend = min(i0 + 64, n);
    float acc = 0.f;
    int cacc = 0;
    int cur = g_batch[i0];
    for (int i = i0; i < iend; i++) {
        int b = g_batch[i];
        if (b != cur) {
            atomicAdd(&g_pool[cur * DH + c], acc);
            if (c == 0) atomicAdd(&g_cnt[cur], cacc);
            acc = 0.f; cacc = 0; cur = b;
        }
        acc += g_hA[(size_t)i * DH + c];
        cacc++;
    }
    atomicAdd(&g_pool[cur * DH + c], acc);
    if (c == 0) atomicAdd(&g_cnt[cur], cacc);
}

// ---------------- classifier head ----------------
__global__ void k_final(const float* __restrict__ Wl, const float* __restrict__ bl,
                        float* __restrict__ out) {
    int t = blockIdx.x * blockDim.x + threadIdx.x;
    if (t >= NG * NC) return;
    int g = t / NC;
    int cls = t % NC;
    float invc = 1.f / fmaxf((float)g_cnt[g], 1.f);
    float dot = 0.f;
#pragma unroll
    for (int d = 0; d < DH; d++) dot += g_pool[g * DH + d] * Wl[d * NC + cls];
    out[t] = dot * invc + bl[cls];
}

// ---------------- host launcher ----------------
extern "C" void kernel_launch(void* const* d_in, const int* in_sizes, int n_in,
                              void* d_out, int out_size) {
    const float* x = (const float*)d_in[0];
    const float* pos = (const float*)d_in[1];
    const void* ei = d_in[2];
    const void* batch = d_in[3];
    const float* W1 = (const float*)d_in[4];
    const float* as1 = (const float*)d_in[5];
    const float* ad1 = (const float*)d_in[6];
    const float* b1 = (const float*)d_in[7];
    const float* W2 = (const float*)d_in[8];
    const float* as2 = (const float*)d_in[9];
    const float* ad2 = (const float*)d_in[10];
    const float* b2 = (const float*)d_in[11];
    const float* W3 = (const float*)d_in[12];
    const float* as3 = (const float*)d_in[13];
    const float* ad3 = (const float*)d_in[14];
    const float* b3 = (const float*)d_in[15];
    const float* Wl = (const float*)d_in[16];
    const float* bl = (const float*)d_in[17];
    float* out = (float*)d_out;

    int n = in_sizes[0];
    int E = in_sizes[2] / 2;
    int nb = (n + 2047) / 2048;
    int nblocks = (n + 7) / 8;

    k_detect<<<1, 256>>>((const unsigned int*)ei, E);
    int initT = n;
    if (initT < NG * DH) initT = NG * DH;
    k_init<<<(initT + 255) / 256, 256>>>(n);
    k_convert_edges<<<(E + 255) / 256, 256>>>(ei, E, n);
    k_convert_batch<<<(n + 255) / 256, 256>>>(batch, n);

    k_scan1<<<nb, 256>>>(n);
    k_scan2<<<1, 32>>>(nb, n);
    k_scan3<<<nb, 256>>>(n);
    k_scatter<<<(E + n + 255) / 256, 256>>>(E, n);

    int tb = (n + 3) / 4;
    int tg = 1184;   // persistent blocks (8/SM)

    // layer 1 input transform -> h16A, asA/adA
    k_transform_in<<<tb, 256>>>(x, pos, W1, as1, ad1, n);
    // aggregate L1 (+bias b1) fused with transform by W2 -> h16B, asB/adB
    k_agg_tr<<<tg, 256>>>(0, 0, b1, W2, as2, ad2, n, nblocks);
    // aggregate L2 (+bias b2) fused with transform by W3 -> h16A, asA/adA
    k_agg_tr<<<tg, 256>>>(1, 0, b2, W3, as3, ad3, n, nblocks);
    // aggregate L3 (+bias b3) final -> g_hA fp32
    k_agg_tr<<<nblocks, 256>>>(0, 1, b3, W3, as3, ad3, n, nblocks);

    int chunks = (n + 63) / 64;
    k_pool<<<(chunks + 3) / 4, 256>>>(n);
    k_final<<<(NG * NC + 255) / 256, 256>>>(Wl, bl, out);
}